// round 6
// baseline (speedup 1.0000x reference)
#include <cuda_runtime.h>
#include <cuda_bf16.h>
#include <cstdint>

// Problem constants
#define Q      1024
#define D      512
#define DU     256                      // D in b16 units (2 int8 each)
#define NPTS   50000
#define BM     128
#define BN     128
#define BKU    32                       // K per iter in b16 units (= 64 int8)
#define ITERS  (DU / BKU)               // 8
#define NTILES ((NPTS + BN - 1) / BN)   // 391
#define PITCH  (NTILES * BN)            // 50048
#define KNN    10
#define PAD    40                       // padded smem row stride in b16 units (80B)

// Scratch (device globals: allocation-free rule)
__device__ float    g_dot[(size_t)Q * PITCH];   // approx sq distances (~205 MB)
__device__ float    g_x2[Q];
__device__ float    g_d2[NPTS];
__device__ float    g_sx[Q];
__device__ float    g_sd[NPTS];
__device__ uint16_t g_xq[(size_t)Q * DU];       // int8 pairs packed in b16 units
__device__ uint16_t g_dq[(size_t)NPTS * DU];

// ---------------------------------------------------------------------------
// helpers
// ---------------------------------------------------------------------------
__device__ __forceinline__ uint32_t smem_u32(const void* p) {
    uint32_t a;
    asm("{ .reg .u64 t; cvta.to.shared.u64 t, %1; cvt.u32.u64 %0, t; }" : "=r"(a) : "l"(p));
    return a;
}
__device__ __forceinline__ void cp_async16(uint32_t saddr, const void* gaddr, uint32_t src_sz) {
    asm volatile("cp.async.cg.shared.global [%0], [%1], 16, %2;"
                 :: "r"(saddr), "l"(gaddr), "r"(src_sz) : "memory");
}
__device__ __forceinline__ void cp_commit() {
    asm volatile("cp.async.commit_group;" ::: "memory");
}
template <int N>
__device__ __forceinline__ void cp_wait() {
    asm volatile("cp.async.wait_group %0;" :: "n"(N) : "memory");
}
__device__ __forceinline__ void ldm_x4(uint32_t& r0, uint32_t& r1, uint32_t& r2, uint32_t& r3,
                                       uint32_t addr) {
    asm volatile("ldmatrix.sync.aligned.m8n8.x4.shared.b16 {%0,%1,%2,%3}, [%4];"
                 : "=r"(r0), "=r"(r1), "=r"(r2), "=r"(r3) : "r"(addr));
}
__device__ __forceinline__ void mma_s8(int& c0, int& c1, int& c2, int& c3,
                                       uint32_t a0, uint32_t a1, uint32_t a2, uint32_t a3,
                                       uint32_t b0, uint32_t b1) {
    asm volatile(
        "mma.sync.aligned.m16n8k32.row.col.s32.s8.s8.s32 "
        "{%0,%1,%2,%3}, {%4,%5,%6,%7}, {%8,%9}, {%0,%1,%2,%3};"
        : "+r"(c0), "+r"(c1), "+r"(c2), "+r"(c3)
        : "r"(a0), "r"(a1), "r"(a2), "r"(a3), "r"(b0), "r"(b1));
}

// ---------------------------------------------------------------------------
// Kernel 0: fused quantize(int8, per-row scale) + row squared norms
// One warp per row. Keeps 16 floats in regs; two warp reductions (sum, max).
// ---------------------------------------------------------------------------
__global__ void quant_norms_kernel(const float* __restrict__ X,
                                   const float* __restrict__ data)
{
    int warp = (blockIdx.x * blockDim.x + threadIdx.x) >> 5;
    int lane = threadIdx.x & 31;
    if (warp >= Q + NPTS) return;

    const float* src;
    uint16_t*    dstq;
    float *dn, *ds;
    int row;
    if (warp < Q) { src = X;    row = warp;     dstq = g_xq; dn = g_x2; ds = g_sx; }
    else          { src = data; row = warp - Q; dstq = g_dq; dn = g_d2; ds = g_sd; }

    const float4* s4 = (const float4*)(src + (size_t)row * D);
    float4 v[4];
    float s = 0.f, m = 0.f;
    #pragma unroll
    for (int it = 0; it < 4; ++it) {
        v[it] = s4[it * 32 + lane];
        const float* f = (const float*)&v[it];
        #pragma unroll
        for (int e = 0; e < 4; ++e) {
            s = fmaf(f[e], f[e], s);
            m = fmaxf(m, fabsf(f[e]));
        }
    }
    #pragma unroll
    for (int off = 16; off; off >>= 1) {
        s += __shfl_xor_sync(0xffffffffu, s, off);
        m  = fmaxf(m, __shfl_xor_sync(0xffffffffu, m, off));
    }
    m = fmaxf(m, 1e-20f);
    const float inv = 127.f / m;

    uint32_t* dq32 = (uint32_t*)(dstq + (size_t)row * DU);
    #pragma unroll
    for (int it = 0; it < 4; ++it) {
        const float* f = (const float*)&v[it];
        uint32_t p = 0;
        #pragma unroll
        for (int e = 0; e < 4; ++e) {
            int qv = __float2int_rn(f[e] * inv);
            qv = max(-127, min(127, qv));
            p |= ((uint32_t)qv & 0xffu) << (e * 8);
        }
        dq32[it * 32 + lane] = p;
    }
    if (lane == 0) { dn[row] = s; ds[row] = m * (1.f / 127.f); }
}

// ---------------------------------------------------------------------------
// Kernel 1: int8 mma.sync GEMM tile (128x128, K=512 int8 = 256 b16 units).
// 8 warps (2m x 4n), warp tile 64x32, m16n8k32 s8. Epilogue writes
// score = max(x2 + d2 - 2*sx*sd*acc, 0) to g_dot.
// ---------------------------------------------------------------------------
__global__ void __launch_bounds__(256, 2) gemm_imma_kernel()
{
    __shared__ __align__(16) uint16_t As[2][BM * PAD];
    __shared__ __align__(16) uint16_t Bs[2][BN * PAD];

    const int tid    = threadIdx.x;
    const int wid    = tid >> 5;
    const int lane   = tid & 31;
    const int warp_m = wid >> 2;    // 0..1
    const int warp_n = wid & 3;     // 0..3
    const int bn     = blockIdx.x * BN;
    const int bm     = blockIdx.y * BM;

    // cp.async mapping: tile = 128 rows x 32 units = 512 16B-chunks, 2/thread
    const int r0 = tid >> 2,         c0 = tid & 3;
    const int r1 = (tid + 256) >> 2, c1 = (tid + 256) & 3;

    const uint32_t sA  = smem_u32(As);
    const uint32_t sB  = smem_u32(Bs);
    const uint32_t aS0 = sA + (r0 * PAD + c0 * 8) * 2;
    const uint32_t aS1 = sA + (r1 * PAD + c1 * 8) * 2;
    const uint32_t bS0 = sB + (r0 * PAD + c0 * 8) * 2;
    const uint32_t bS1 = sB + (r1 * PAD + c1 * 8) * 2;
    const size_t   aG0 = (size_t)(bm + r0) * DU + c0 * 8;
    const size_t   aG1 = (size_t)(bm + r1) * DU + c1 * 8;
    const size_t   bG0 = (size_t)(bn + r0) * DU + c0 * 8;
    const size_t   bG1 = (size_t)(bn + r1) * DU + c1 * 8;
    const uint32_t bV0 = (bn + r0 < NPTS) ? 16u : 0u;
    const uint32_t bV1 = (bn + r1 < NPTS) ? 16u : 0u;
    const uint32_t BUFA = BM * PAD * 2;   // bytes per buffer
    const uint32_t BUFB = BN * PAD * 2;

    // ldmatrix per-lane bases (b16-unit addressing, same mapping as proven bf16)
    const uint32_t aLd = sA + (((warp_m * 64) + (lane & 15)) * PAD + (lane >> 4) * 8) * 2;
    const uint32_t bLd = sB + (((warp_n * 32) + (lane & 7)) * PAD + (lane >> 3) * 8) * 2;

    int acc[4][4][4];
    #pragma unroll
    for (int i = 0; i < 4; ++i)
        #pragma unroll
        for (int j = 0; j < 4; ++j)
            #pragma unroll
            for (int e = 0; e < 4; ++e)
                acc[i][j][e] = 0;

    // prologue: stage 0 -> buf 0
    cp_async16(aS0, g_xq + aG0, 16);
    cp_async16(aS1, g_xq + aG1, 16);
    cp_async16(bS0, g_dq + bG0, bV0);
    cp_async16(bS1, g_dq + bG1, bV1);
    cp_commit();

    for (int it = 0; it < ITERS; ++it) {
        const int      buf  = it & 1;
        const uint32_t offA = buf ? BUFA : 0;
        const uint32_t offB = buf ? BUFB : 0;

        cp_wait<0>();
        __syncthreads();   // stage data visible + prev compute done (buf free)

        if (it + 1 < ITERS) {
            const int      nb = (it + 1) & 1;
            const uint32_t nA = nb ? BUFA : 0;
            const uint32_t nB = nb ? BUFB : 0;
            const int      k0 = (it + 1) * BKU;
            cp_async16(aS0 + nA, g_xq + aG0 + k0, 16);
            cp_async16(aS1 + nA, g_xq + aG1 + k0, 16);
            cp_async16(bS0 + nB, g_dq + bG0 + k0, bV0);
            cp_async16(bS1 + nB, g_dq + bG1 + k0, bV1);
            cp_commit();
        }

        // B fragments: x4 per n-tile covers both ksteps
        uint32_t b[4][4];
        #pragma unroll
        for (int nt = 0; nt < 4; ++nt)
            ldm_x4(b[nt][0], b[nt][1], b[nt][2], b[nt][3],
                   bLd + offB + (nt * 8 * PAD) * 2);

        #pragma unroll
        for (int ks = 0; ks < 2; ++ks) {
            uint32_t a[4][4];
            #pragma unroll
            for (int mt = 0; mt < 4; ++mt)
                ldm_x4(a[mt][0], a[mt][1], a[mt][2], a[mt][3],
                       aLd + offA + (mt * 16 * PAD + ks * 16) * 2);
            #pragma unroll
            for (int mt = 0; mt < 4; ++mt)
                #pragma unroll
                for (int nt = 0; nt < 4; ++nt)
                    mma_s8(acc[mt][nt][0], acc[mt][nt][1], acc[mt][nt][2], acc[mt][nt][3],
                           a[mt][0], a[mt][1], a[mt][2], a[mt][3],
                           b[nt][ks * 2], b[nt][ks * 2 + 1]);
        }
    }
    __syncthreads();

    // stage per-row x2/sx and per-col d2/sd (smem buffers dead)
    float* s_x2 = (float*)As;
    float* s_sx = s_x2 + BM;
    float* s_d2 = s_sx + BM;
    float* s_sd = s_d2 + BN;
    if (tid < BM) {
        s_x2[tid] = g_x2[bm + tid];
        s_sx[tid] = g_sx[bm + tid];
    } else {
        int gn = bn + tid - BM;
        bool ok = gn < NPTS;
        s_d2[tid - BM] = ok ? g_d2[gn] : __int_as_float(0x7f800000);
        s_sd[tid - BM] = ok ? g_sd[gn] : 0.f;
    }
    __syncthreads();

    #pragma unroll
    for (int mt = 0; mt < 4; ++mt) {
        const int rA = warp_m * 64 + mt * 16 + (lane >> 2);
        const float x2a = s_x2[rA],     sxa = s_sx[rA];
        const float x2b = s_x2[rA + 8], sxb = s_sx[rA + 8];
        float* rowA = g_dot + (size_t)(bm + rA) * PITCH + bn;
        float* rowB = rowA + (size_t)8 * PITCH;
        #pragma unroll
        for (int nt = 0; nt < 4; ++nt) {
            const int cl = warp_n * 32 + nt * 8 + (lane & 3) * 2;
            const float d2a = s_d2[cl],  sda = s_sd[cl];
            const float d2b = s_d2[cl + 1], sdb = s_sd[cl + 1];
            float2 v0, v1;
            v0.x = fmaxf(fmaf(-2.f * sxa * sda, (float)acc[mt][nt][0], x2a + d2a), 0.f);
            v0.y = fmaxf(fmaf(-2.f * sxa * sdb, (float)acc[mt][nt][1], x2a + d2b), 0.f);
            v1.x = fmaxf(fmaf(-2.f * sxb * sda, (float)acc[mt][nt][2], x2b + d2a), 0.f);
            v1.y = fmaxf(fmaf(-2.f * sxb * sdb, (float)acc[mt][nt][3], x2b + d2b), 0.f);
            *(float2*)(rowA + cl) = v0;
            *(float2*)(rowB + cl) = v1;
        }
    }
}

// ---------------------------------------------------------------------------
// Kernel 2: per-query approx top-32 -> exact fp32 re-rank -> top-10 -> mode
// One block per query, 256 threads.
// ---------------------------------------------------------------------------
#define KLOC 8    // per-thread approx candidates
#define KSEL 32   // approx candidates re-ranked exactly

__global__ void __launch_bounds__(256) select_kernel(const float* __restrict__ X,
                                                     const float* __restrict__ data,
                                                     const int* __restrict__ t32,
                                                     float* __restrict__ out)
{
    const int q    = blockIdx.x;
    const int tid  = threadIdx.x;
    const int wid  = tid >> 5;
    const int lane = tid & 31;

    __shared__ float sx[D];
    sx[tid]       = X[(size_t)q * D + tid];
    sx[tid + 256] = X[(size_t)q * D + 256 + tid];

    // Phase 1: per-thread top-8 over approx scores (float4 reads)
    const float4* row4 = (const float4*)(g_dot + (size_t)q * PITCH);
    const unsigned long long MAXK = ~0ull;
    unsigned long long best[KLOC];
    #pragma unroll
    for (int i = 0; i < KLOC; ++i) best[i] = MAXK;

    for (int j4 = tid; j4 < PITCH / 4; j4 += 256) {
        float4 v = row4[j4];
        const float* f = (const float*)&v;
        #pragma unroll
        for (int e = 0; e < 4; ++e) {
            unsigned long long key =
                ((unsigned long long)__float_as_uint(f[e]) << 32) | (unsigned)(j4 * 4 + e);
            if (key < best[KLOC - 1]) {
                best[KLOC - 1] = key;
                #pragma unroll
                for (int i = KLOC - 1; i >= 1; --i) {
                    if (best[i] < best[i - 1]) {
                        unsigned long long t = best[i - 1];
                        best[i - 1] = best[i];
                        best[i] = t;
                    }
                }
            }
        }
    }

    // Phase 2: 32 rounds of block-wide min-merge (warp shuffles, 2 bars/round)
    __shared__ unsigned long long wmin[8];
    __shared__ unsigned long long winner;
    __shared__ unsigned long long topk[KSEL];
    int ptr = 0;
    for (int r = 0; r < KSEL; ++r) {
        unsigned long long my = (ptr < KLOC) ? best[ptr] : MAXK;
        unsigned long long wm = my;
        #pragma unroll
        for (int off = 16; off; off >>= 1) {
            unsigned long long o = __shfl_xor_sync(0xffffffffu, wm, off);
            if (o < wm) wm = o;
        }
        if (lane == 0) wmin[wid] = wm;
        __syncthreads();
        if (tid == 0) {
            unsigned long long w = wmin[0];
            #pragma unroll
            for (int i = 1; i < 8; ++i)
                if (wmin[i] < w) w = wmin[i];
            winner = w;
            topk[r] = w;
        }
        __syncthreads();
        unsigned long long w = winner;
        if (my == w && my != MAXK) ++ptr;   // keys unique (idx in low bits)
    }

    // Phase 3: exact fp32 re-rank of the 32 candidates (one warp each)
    __shared__ unsigned long long ex[KSEL];
    const float x2q = g_x2[q];
    for (int t = wid; t < KSEL; t += 8) {
        unsigned c = (unsigned)(topk[t] & 0xffffffffu);
        const float* dr = data + (size_t)c * D;
        float dot = 0.f;
        #pragma unroll 4
        for (int k = lane; k < D; k += 32)
            dot = fmaf(sx[k], dr[k], dot);
        #pragma unroll
        for (int off = 16; off; off >>= 1)
            dot += __shfl_down_sync(0xffffffffu, dot, off);
        if (lane == 0) {
            float sq = fmaxf(fmaf(-2.f, dot, x2q + g_d2[c]), 0.f);
            ex[t] = ((unsigned long long)__float_as_uint(sq) << 32) | c;
        }
    }
    __syncthreads();

    // Phase 4: top-10 of 32 (selection), labels, mode (smallest label on tie)
    if (tid == 0) {
        unsigned long long a[KSEL];
        #pragma unroll
        for (int i = 0; i < KSEL; ++i) a[i] = ex[i];
        int lab[KNN];
        #pragma unroll
        for (int r = 0; r < KNN; ++r) {
            int bi = r;
            for (int i = r + 1; i < KSEL; ++i)
                if (a[i] < a[bi]) bi = i;
            unsigned long long t = a[r]; a[r] = a[bi]; a[bi] = t;
            lab[r] = -1;  // filled below
        }

        // targets element width probe (int32 vs int64 little-endian)
        int stride = 2;
        #pragma unroll
        for (int i = 1; i < 64; i += 2)
            if (t32[i] != 0) { stride = 1; break; }

        #pragma unroll
        for (int r = 0; r < KNN; ++r)
            lab[r] = t32[(size_t)(unsigned)(a[r] & 0xffffffffu) * stride];

        int bestLab = 0x7fffffff, bestCnt = 0;
        #pragma unroll
        for (int i = 0; i < KNN; ++i) {
            int cnt = 0;
            #pragma unroll
            for (int j = 0; j < KNN; ++j)
                cnt += (lab[j] == lab[i]);
            if (cnt > bestCnt || (cnt == bestCnt && lab[i] < bestLab)) {
                bestCnt = cnt;
                bestLab = lab[i];
            }
        }
        out[q] = (float)bestLab;
    }
}

// ---------------------------------------------------------------------------
extern "C" void kernel_launch(void* const* d_in, const int* in_sizes, int n_in,
                              void* d_out, int out_size)
{
    const float* X       = (const float*)d_in[0];
    const float* data    = (const float*)d_in[1];
    const int*   targets = (const int*)d_in[2];
    float*       out     = (float*)d_out;

    (void)in_sizes; (void)n_in; (void)out_size;

    // quantize + norms: warp per row
    int nwarps  = Q + NPTS;
    int nblocks = (nwarps + 7) / 8;
    quant_norms_kernel<<<nblocks, 256>>>(X, data);

    // IMMA GEMM: 391 N-tiles x 8 M-tiles
    dim3 grid(NTILES, Q / BM);
    gemm_imma_kernel<<<grid, 256>>>();

    // approx select + exact re-rank + mode
    select_kernel<<<Q, 256>>>(X, data, targets, out);
}

// round 8
// speedup vs baseline: 1.4223x; 1.4223x over previous
#include <cuda_runtime.h>
#include <cuda_bf16.h>
#include <cuda_fp16.h>
#include <cstdint>

// Problem constants
#define Q      1024
#define D      512
#define NPTS   50000
#define BM     128
#define BN     128
#define BK     32
#define ITERS  (D / BK)                 // 16
#define NSTAGE 4
#define NTILES ((NPTS + BN - 1) / BN)   // 391
#define PITCH  (NTILES * BN)            // 50048
#define KNN    10
#define PAD    40                       // padded smem row stride in bf16 (80B)

// Scratch (device globals: allocation-free rule)
__device__ __half         g_dot[(size_t)Q * PITCH];  // approx sq distances (~102 MB)
__device__ float          g_x2[Q];
__device__ float          g_d2[NPTS];
__device__ __nv_bfloat16  g_xb[(size_t)Q * D];
__device__ __nv_bfloat16  g_db[(size_t)NPTS * D];

// ---------------------------------------------------------------------------
// helpers
// ---------------------------------------------------------------------------
__device__ __forceinline__ uint32_t smem_u32(const void* p) {
    uint32_t a;
    asm("{ .reg .u64 t; cvta.to.shared.u64 t, %1; cvt.u32.u64 %0, t; }" : "=r"(a) : "l"(p));
    return a;
}
__device__ __forceinline__ void cp_async16(uint32_t saddr, const void* gaddr, uint32_t src_sz) {
    asm volatile("cp.async.cg.shared.global [%0], [%1], 16, %2;"
                 :: "r"(saddr), "l"(gaddr), "r"(src_sz) : "memory");
}
__device__ __forceinline__ void cp_commit() {
    asm volatile("cp.async.commit_group;" ::: "memory");
}
template <int N>
__device__ __forceinline__ void cp_wait() {
    asm volatile("cp.async.wait_group %0;" :: "n"(N) : "memory");
}
__device__ __forceinline__ void ldm_x4(uint32_t& r0, uint32_t& r1, uint32_t& r2, uint32_t& r3,
                                       uint32_t addr) {
    asm volatile("ldmatrix.sync.aligned.m8n8.x4.shared.b16 {%0,%1,%2,%3}, [%4];"
                 : "=r"(r0), "=r"(r1), "=r"(r2), "=r"(r3) : "r"(addr));
}
__device__ __forceinline__ void mma_bf16(float& c0, float& c1, float& c2, float& c3,
                                         uint32_t a0, uint32_t a1, uint32_t a2, uint32_t a3,
                                         uint32_t b0, uint32_t b1) {
    asm volatile(
        "mma.sync.aligned.m16n8k16.row.col.f32.bf16.bf16.f32 "
        "{%0,%1,%2,%3}, {%4,%5,%6,%7}, {%8,%9}, {%0,%1,%2,%3};"
        : "+f"(c0), "+f"(c1), "+f"(c2), "+f"(c3)
        : "r"(a0), "r"(a1), "r"(a2), "r"(a3), "r"(b0), "r"(b1));
}

// ---------------------------------------------------------------------------
// Kernel 0: fused fp32->bf16 convert + row squared norms (warp per row)
// ---------------------------------------------------------------------------
__global__ void convert_norms_kernel(const float* __restrict__ X,
                                     const float* __restrict__ data)
{
    int warp = (blockIdx.x * blockDim.x + threadIdx.x) >> 5;
    int lane = threadIdx.x & 31;
    if (warp >= Q + NPTS) return;

    const float*   src;
    __nv_bfloat16* dstb;
    float*         dstn;
    int row;
    if (warp < Q) { src = X;    row = warp;     dstb = g_xb; dstn = g_x2; }
    else          { src = data; row = warp - Q; dstb = g_db; dstn = g_d2; }

    const float4* s4 = (const float4*)(src + (size_t)row * D);
    uint2*        d8 = (uint2*)(dstb + (size_t)row * D);

    float s = 0.f;
    #pragma unroll
    for (int it = 0; it < 4; ++it) {
        int i = it * 32 + lane;
        float4 v = s4[i];
        s = fmaf(v.x, v.x, s);
        s = fmaf(v.y, v.y, s);
        s = fmaf(v.z, v.z, s);
        s = fmaf(v.w, v.w, s);
        __nv_bfloat162 h0 = __floats2bfloat162_rn(v.x, v.y);
        __nv_bfloat162 h1 = __floats2bfloat162_rn(v.z, v.w);
        uint2 w;
        w.x = *reinterpret_cast<uint32_t*>(&h0);
        w.y = *reinterpret_cast<uint32_t*>(&h1);
        d8[i] = w;
    }
    #pragma unroll
    for (int off = 16; off; off >>= 1)
        s += __shfl_down_sync(0xffffffffu, s, off);
    if (lane == 0) dstn[row] = s;
}

// ---------------------------------------------------------------------------
// Kernel 1: bf16 mma.sync GEMM tile (128x128, K=512), 4-stage cp.async
// pipeline with ONE __syncthreads per K-iter. Epilogue writes
// half( max(x2 + d2 - 2*dot, 0) ) to g_dot.
// Dynamic smem: NSTAGE stages of [A 10240B][B 10240B].
// ---------------------------------------------------------------------------
#define ASZ    (BM * PAD * 2)            // 10240 bytes
#define BSZ    (BN * PAD * 2)            // 10240 bytes
#define STAGE  (ASZ + BSZ)               // 20480 bytes
#define GSMEM  (NSTAGE * STAGE)          // 81920 bytes

__global__ void __launch_bounds__(256, 2) gemm_mma_kernel()
{
    extern __shared__ __align__(16) uint16_t dsm[];

    const int tid    = threadIdx.x;
    const int wid    = tid >> 5;
    const int lane   = tid & 31;
    const int warp_m = wid >> 2;    // 0..1
    const int warp_n = wid & 3;     // 0..3
    const int bn     = blockIdx.x * BN;
    const int bm     = blockIdx.y * BM;

    // cp.async per-thread mapping: 512 16B-chunks per operand tile, 2/thread
    const int r0 = tid >> 2,         c0 = tid & 3;
    const int r1 = (tid + 256) >> 2, c1 = (tid + 256) & 3;

    const uint32_t s0  = smem_u32(dsm);
    const uint32_t aS0 = s0 + (r0 * PAD + c0 * 8) * 2;
    const uint32_t aS1 = s0 + (r1 * PAD + c1 * 8) * 2;
    const uint32_t bS0 = s0 + ASZ + (r0 * PAD + c0 * 8) * 2;
    const uint32_t bS1 = s0 + ASZ + (r1 * PAD + c1 * 8) * 2;
    const size_t   aG0 = (size_t)(bm + r0) * D + c0 * 8;
    const size_t   aG1 = (size_t)(bm + r1) * D + c1 * 8;
    const size_t   bG0 = (size_t)(bn + r0) * D + c0 * 8;
    const size_t   bG1 = (size_t)(bn + r1) * D + c1 * 8;
    const uint32_t bV0 = (bn + r0 < NPTS) ? 16u : 0u;
    const uint32_t bV1 = (bn + r1 < NPTS) ? 16u : 0u;

    // ldmatrix per-lane bases (proven R5 mapping)
    const uint32_t aLd = s0 + (((warp_m * 64) + (lane & 15)) * PAD + (lane >> 4) * 8) * 2;
    const uint32_t bLd = s0 + ASZ + (((warp_n * 32) + (lane & 7)) * PAD + (lane >> 3) * 8) * 2;

    float acc[4][4][4];
    #pragma unroll
    for (int i = 0; i < 4; ++i)
        #pragma unroll
        for (int j = 0; j < 4; ++j)
            #pragma unroll
            for (int e = 0; e < 4; ++e)
                acc[i][j][e] = 0.f;

    // prologue: stages 0..NSTAGE-2
    #pragma unroll
    for (int s = 0; s < NSTAGE - 1; ++s) {
        const uint32_t off = s * STAGE;
        const int      k0  = s * BK;
        cp_async16(aS0 + off, g_xb + aG0 + k0, 16);
        cp_async16(aS1 + off, g_xb + aG1 + k0, 16);
        cp_async16(bS0 + off, g_db + bG0 + k0, bV0);
        cp_async16(bS1 + off, g_db + bG1 + k0, bV1);
        cp_commit();
    }

    for (int it = 0; it < ITERS; ++it) {
        cp_wait<NSTAGE - 2>();
        __syncthreads();               // stage `it` visible to all; buf (it-1)%S free

        const int ps = it + NSTAGE - 1;
        if (ps < ITERS) {
            const uint32_t off = (ps & (NSTAGE - 1)) * STAGE;
            const int      k0  = ps * BK;
            cp_async16(aS0 + off, g_xb + aG0 + k0, 16);
            cp_async16(aS1 + off, g_xb + aG1 + k0, 16);
            cp_async16(bS0 + off, g_db + bG0 + k0, bV0);
            cp_async16(bS1 + off, g_db + bG1 + k0, bV1);
        }
        cp_commit();                   // commit (possibly empty) keeps group count aligned

        const uint32_t off = (it & (NSTAGE - 1)) * STAGE;

        // B fragments: one x4 per n-tile covers k 0..31
        uint32_t b[4][4];
        #pragma unroll
        for (int nt = 0; nt < 4; ++nt)
            ldm_x4(b[nt][0], b[nt][1], b[nt][2], b[nt][3],
                   bLd + off + (nt * 8 * PAD) * 2);

        #pragma unroll
        for (int ks = 0; ks < 2; ++ks) {
            uint32_t a[4][4];
            #pragma unroll
            for (int mt = 0; mt < 4; ++mt)
                ldm_x4(a[mt][0], a[mt][1], a[mt][2], a[mt][3],
                       aLd + off + (mt * 16 * PAD + ks * 16) * 2);
            #pragma unroll
            for (int mt = 0; mt < 4; ++mt)
                #pragma unroll
                for (int nt = 0; nt < 4; ++nt)
                    mma_bf16(acc[mt][nt][0], acc[mt][nt][1], acc[mt][nt][2], acc[mt][nt][3],
                             a[mt][0], a[mt][1], a[mt][2], a[mt][3],
                             b[nt][ks * 2], b[nt][ks * 2 + 1]);
        }
    }
    __syncthreads();

    // stage x2 (local m) and d2 (local n, +inf pad) in smem (buffers dead)
    float* s_x2 = (float*)dsm;
    float* s_d2 = s_x2 + BM;
    if (tid < BM) s_x2[tid] = g_x2[bm + tid];
    else if (tid < BM + BN) {
        int gn = bn + tid - BM;
        s_d2[tid - BM] = (gn < NPTS) ? g_d2[gn] : __int_as_float(0x7f800000);
    }
    __syncthreads();

    // epilogue: c0,c1 -> row rA cols cl,cl+1 ; c2,c3 -> row rA+8 (half2 stores)
    #pragma unroll
    for (int mt = 0; mt < 4; ++mt) {
        const int rA = warp_m * 64 + mt * 16 + (lane >> 2);
        const float x2a = s_x2[rA];
        const float x2b = s_x2[rA + 8];
        __half* rowA = g_dot + (size_t)(bm + rA) * PITCH + bn;
        __half* rowB = rowA + (size_t)8 * PITCH;
        #pragma unroll
        for (int nt = 0; nt < 4; ++nt) {
            const int cl = warp_n * 32 + nt * 8 + (lane & 3) * 2;
            const float d2a = s_d2[cl], d2b = s_d2[cl + 1];
            float f00 = fmaxf(fmaf(-2.f, acc[mt][nt][0], x2a + d2a), 0.f);
            float f01 = fmaxf(fmaf(-2.f, acc[mt][nt][1], x2a + d2b), 0.f);
            float f10 = fmaxf(fmaf(-2.f, acc[mt][nt][2], x2b + d2a), 0.f);
            float f11 = fmaxf(fmaf(-2.f, acc[mt][nt][3], x2b + d2b), 0.f);
            *(__half2*)(rowA + cl) = __floats2half2_rn(f00, f01);
            *(__half2*)(rowB + cl) = __floats2half2_rn(f10, f11);
        }
    }
}

// ---------------------------------------------------------------------------
// Kernel 2: per-query approx top-32 (half scores, 32-bit keys)
//           -> exact fp32 re-rank -> top-10 -> mode.
// One block per query, 256 threads.
// ---------------------------------------------------------------------------
#define KLOC 8    // per-thread approx candidates
#define KSEL 32   // approx candidates re-ranked exactly

__global__ void __launch_bounds__(256) select_kernel(const float* __restrict__ X,
                                                     const float* __restrict__ data,
                                                     const int* __restrict__ t32,
                                                     float* __restrict__ out)
{
    const int q    = blockIdx.x;
    const int tid  = threadIdx.x;
    const int wid  = tid >> 5;
    const int lane = tid & 31;

    __shared__ float sx[D];
    sx[tid]       = X[(size_t)q * D + tid];
    sx[tid + 256] = X[(size_t)q * D + 256 + tid];

    // Phase 1: per-thread top-8 over half scores; key = (hbits<<16)|idx
    const uint4* row16 = (const uint4*)(g_dot + (size_t)q * PITCH);   // 8 halves each
    const uint32_t MAXK = 0xffffffffu;
    uint32_t best[KLOC];
    #pragma unroll
    for (int i = 0; i < KLOC; ++i) best[i] = MAXK;

    for (int j = tid; j < PITCH / 8; j += 256) {
        uint4 v = row16[j];
        const uint32_t w[4] = {v.x, v.y, v.z, v.w};
        #pragma unroll
        for (int e = 0; e < 8; ++e) {
            uint32_t h = (w[e >> 1] >> ((e & 1) * 16)) & 0xffffu;
            uint32_t key = (h << 16) | (uint32_t)(j * 8 + e);
            if (key < best[KLOC - 1]) {
                best[KLOC - 1] = key;
                #pragma unroll
                for (int i = KLOC - 1; i >= 1; --i) {
                    if (best[i] < best[i - 1]) {
                        uint32_t t = best[i - 1];
                        best[i - 1] = best[i];
                        best[i] = t;
                    }
                }
            }
        }
    }

    // Phase 2: 32 rounds of block-wide min-merge (shuffle + 2 bars/round)
    __shared__ uint32_t wmin[8];
    __shared__ uint32_t winner;
    __shared__ uint32_t topk[KSEL];
    int ptr = 0;
    for (int r = 0; r < KSEL; ++r) {
        uint32_t my = (ptr < KLOC) ? best[ptr] : MAXK;
        uint32_t wm = my;
        #pragma unroll
        for (int off = 16; off; off >>= 1)
            wm = min(wm, __shfl_xor_sync(0xffffffffu, wm, off));
        if (lane == 0) wmin[wid] = wm;
        __syncthreads();
        if (tid == 0) {
            uint32_t w = wmin[0];
            #pragma unroll
            for (int i = 1; i < 8; ++i) w = min(w, wmin[i]);
            winner = w;
            topk[r] = w;
        }
        __syncthreads();
        if (my == winner && my != MAXK) ++ptr;   // keys unique (idx in low bits)
    }

    // Phase 3: exact fp32 re-rank of the 32 candidates (one warp each, strided)
    __shared__ unsigned long long ex[KSEL];
    const float x2q = g_x2[q];
    for (int t = wid; t < KSEL; t += 8) {
        unsigned c = topk[t] & 0xffffu;
        const float* dr = data + (size_t)c * D;
        float dot = 0.f;
        #pragma unroll 4
        for (int k = lane; k < D; k += 32)
            dot = fmaf(sx[k], dr[k], dot);
        #pragma unroll
        for (int off = 16; off; off >>= 1)
            dot += __shfl_down_sync(0xffffffffu, dot, off);
        if (lane == 0) {
            float sq = fmaxf(fmaf(-2.f, dot, x2q + g_d2[c]), 0.f);
            ex[t] = ((unsigned long long)__float_as_uint(sq) << 32) | c;
        }
    }
    __syncthreads();

    // Phase 4: top-10 of 32 by selection, labels, mode (smallest label on tie)
    if (tid == 0) {
        unsigned long long a[KSEL];
        #pragma unroll
        for (int i = 0; i < KSEL; ++i) a[i] = ex[i];
        #pragma unroll
        for (int r = 0; r < KNN; ++r) {
            int bi = r;
            for (int i = r + 1; i < KSEL; ++i)
                if (a[i] < a[bi]) bi = i;
            unsigned long long t = a[r]; a[r] = a[bi]; a[bi] = t;
        }

        // targets element width probe (int32 vs int64 little-endian)
        int stride = 2;
        #pragma unroll
        for (int i = 1; i < 64; i += 2)
            if (t32[i] != 0) { stride = 1; break; }

        int lab[KNN];
        #pragma unroll
        for (int r = 0; r < KNN; ++r)
            lab[r] = t32[(size_t)(unsigned)(a[r] & 0xffffffffu) * stride];

        int bestLab = 0x7fffffff, bestCnt = 0;
        #pragma unroll
        for (int i = 0; i < KNN; ++i) {
            int cnt = 0;
            #pragma unroll
            for (int j = 0; j < KNN; ++j)
                cnt += (lab[j] == lab[i]);
            if (cnt > bestCnt || (cnt == bestCnt && lab[i] < bestLab)) {
                bestCnt = cnt;
                bestLab = lab[i];
            }
        }
        out[q] = (float)bestLab;
    }
}

// ---------------------------------------------------------------------------
extern "C" void kernel_launch(void* const* d_in, const int* in_sizes, int n_in,
                              void* d_out, int out_size)
{
    const float* X       = (const float*)d_in[0];
    const float* data    = (const float*)d_in[1];
    const int*   targets = (const int*)d_in[2];
    float*       out     = (float*)d_out;

    (void)in_sizes; (void)n_in; (void)out_size;

    // allow 80KB dynamic smem (idempotent; not a stream op — capture-safe)
    cudaFuncSetAttribute((const void*)gemm_mma_kernel,
                         cudaFuncAttributeMaxDynamicSharedMemorySize, GSMEM);

    // convert + norms: warp per row
    int nwarps  = Q + NPTS;
    int nblocks = (nwarps + 7) / 8;
    convert_norms_kernel<<<nblocks, 256>>>(X, data);

    // mma.sync GEMM: 391 N-tiles x 8 M-tiles, 4-stage pipeline
    dim3 grid(NTILES, Q / BM);
    gemm_mma_kernel<<<grid, 256, GSMEM>>>();

    // approx select + exact re-rank + mode
    select_kernel<<<Q, 256>>>(X, data, targets, out);
}